// round 8
// baseline (speedup 1.0000x reference)
#include <cuda_runtime.h>
#include <cuda_fp16.h>
#include <stdint.h>

// Problem dims
#define Bsz 512
#define Tsz 1024
#define Csz 64
#define Hsz 128

static const int BTILE   = 64;    // batch per CTA
static const int NTHR    = 512;   // 16 warps
static const int HSTRIDE = 136;   // halves per batch row of h (128 + 8 pad, conflict-free)

// dynamic smem layout (bytes)
//   [0, 131072)            W_hh fp16 A-fragment-ready  (16 warps * 2 mtiles * 8 ksteps * 32 lanes * 16B)
//   [131072, +17408)       h_sm fp16   (64 x 136 halves)
//   [148480, +256)         x_sm fp32   (64)
//   [148736, +32768)       hf_sm fp32  (64 x 128) final-step h for fc
static const int SMEM_W  = 131072;
static const int SMEM_H  = SMEM_W;
static const int SMEM_X  = SMEM_H + 17408;
static const int SMEM_HF = SMEM_X + 256;
static const int SMEM_TOTAL = SMEM_HF + 32768;   // 181504 B

__device__ __forceinline__ unsigned pack2(float a, float b) {
    __half2 h = __floats2half2_rn(a, b);   // low = a, high = b
    return *reinterpret_cast<unsigned*>(&h);
}

__device__ __forceinline__ void mma16816(float* c, uint4 a, unsigned b0, unsigned b1) {
    asm volatile(
        "mma.sync.aligned.m16n8k16.row.col.f32.f16.f16.f32 "
        "{%0,%1,%2,%3}, {%4,%5,%6,%7}, {%8,%9}, {%0,%1,%2,%3};\n"
        : "+f"(c[0]), "+f"(c[1]), "+f"(c[2]), "+f"(c[3])
        : "r"(a.x), "r"(a.y), "r"(a.z), "r"(a.w), "r"(b0), "r"(b1));
}

__device__ __forceinline__ float sigf(float x) {
    // exact-ish: EX2 + RCP (overflow-safe: exp->inf => rcp->0)
    return __fdividef(1.0f, 1.0f + __expf(-x));
}
__device__ __forceinline__ float tanf_(float x) {
    // tanh(x) = 2*sigmoid(2x) - 1 (overflow-safe, no NaN)
    return 2.0f * __fdividef(1.0f, 1.0f + __expf(-2.0f * x)) - 1.0f;
}

extern __shared__ unsigned char smem_raw[];

__global__ void __launch_bounds__(NTHR, 1)
lstm_fused_kernel(const float* __restrict__ x,     // [B,T,C]
                  const float* __restrict__ W_ih,  // [C,4H]
                  const float* __restrict__ W_hh,  // [C,4H,H]
                  const float* __restrict__ b_ih,  // [C,4H]
                  const float* __restrict__ b_hh,  // [C,4H]
                  const float* __restrict__ W_fc,  // [C,H]
                  const float* __restrict__ b_fc,  // [C]
                  float* __restrict__ out)         // [B,C]
{
    const int btile = blockIdx.x;   // 0..7
    const int ch    = blockIdx.y;   // 0..63
    const int tid   = threadIdx.x;
    const int w     = tid >> 5;     // warp 0..15
    const int l     = tid & 31;
    const int gid   = l >> 2;       // 0..7
    const int q     = l & 3;        // 0..3

    __half* Wfr  = (__half*)(smem_raw);
    __half* h_sm = (__half*)(smem_raw + SMEM_H);
    float*  x_sm = (float*)(smem_raw + SMEM_X);
    float*  hf_sm= (float*)(smem_raw + SMEM_HF);

    // hidden unit owned by this lane group
    const int j = 8 * w + gid;

    // ---- Stage W_hh[ch] into fp16 A-fragment-ready smem with gate-interleaved rows ----
    // warp w, mtile 0 rows: [i_j (0-7), f_j (8-15)]; mtile 1: [g_j, o_j], j = 8w + (row%8)
    {
        const float* Wc = W_hh + (size_t)ch * (4 * Hsz * Hsz);
        #pragma unroll
        for (int mt = 0; mt < 2; ++mt) {
            #pragma unroll
            for (int ks = 0; ks < 8; ++ks) {
                uint4 frag;
                unsigned u[4];
                #pragma unroll
                for (int p = 0; p < 4; ++p) {
                    // a0:(gid, 2q+{0,1}) a1:(gid+8, 2q) a2:(gid, 2q+8) a3:(gid+8, 2q+8)
                    int r16 = (p & 1) ? (gid + 8) : gid;
                    int kk  = ks * 16 + q * 2 + ((p & 2) ? 8 : 0);
                    int G   = mt * 2 + (r16 >= 8 ? 1 : 0);
                    int row = G * 128 + 8 * w + (r16 & 7);
                    float2 v = *(const float2*)(Wc + row * Hsz + kk);
                    u[p] = pack2(v.x, v.y);
                }
                frag.x = u[0]; frag.y = u[1]; frag.z = u[2]; frag.w = u[3];
                int fidx = ((w * 2 + mt) * 8 + ks) * 32 + l;
                *(uint4*)(Wfr + fidx * 8) = frag;
            }
        }
    }

    // per-lane input weight + combined bias for its 4 gate rows
    float wih[4], bia[4];
    #pragma unroll
    for (int G = 0; G < 4; ++G) {
        int row = G * 128 + j;
        wih[G] = W_ih[ch * 512 + row];
        bia[G] = b_ih[ch * 512 + row] + b_hh[ch * 512 + row];
    }

    // zero h0
    for (int i = tid; i < BTILE * HSTRIDE; i += NTHR) h_sm[i] = __float2half(0.0f);

    float cst[16];
    #pragma unroll
    for (int i = 0; i < 16; ++i) cst[i] = 0.0f;

    const float* xb = x + ((size_t)(btile * 64) * Tsz) * Csz + ch;

    __syncthreads();

    #pragma unroll 1
    for (int t = 0; t < Tsz; ++t) {
        // issue x gather early (consumed after MMA phase)
        float xv = 0.0f;
        if (tid < 64) xv = __ldg(xb + ((size_t)tid * Tsz + t) * Csz);

        float acc[2][8][4];
        #pragma unroll
        for (int mt = 0; mt < 2; ++mt)
            #pragma unroll
            for (int n = 0; n < 8; ++n)
                #pragma unroll
                for (int r = 0; r < 4; ++r) acc[mt][n][r] = 0.0f;

        // gates[512x64] = W_hh * h  via HMMA; reads h_sm + Wfr
        #pragma unroll
        for (int ks = 0; ks < 8; ++ks) {
            uint4 A0 = *(const uint4*)(Wfr + (((w * 2 + 0) * 8 + ks) * 32 + l) * 8);
            uint4 A1 = *(const uint4*)(Wfr + (((w * 2 + 1) * 8 + ks) * 32 + l) * 8);
            #pragma unroll
            for (int n = 0; n < 8; ++n) {
                const __half* hp = h_sm + (n * 8 + gid) * HSTRIDE + ks * 16 + q * 2;
                unsigned b0 = *(const unsigned*)(hp);
                unsigned b1 = *(const unsigned*)(hp + 8);
                mma16816(acc[0][n], A0, b0, b1);
                mma16816(acc[1][n], A1, b0, b1);
            }
        }

        if (tid < 64) x_sm[tid] = xv;
        __syncthreads();   // all h_t reads done; x_sm visible

        const bool last = (t == Tsz - 1);
        #pragma unroll
        for (int n = 0; n < 8; ++n) {
            #pragma unroll
            for (int s = 0; s < 2; ++s) {
                int b = n * 8 + q * 2 + s;
                float xx = x_sm[b];
                // C-frag: c0/c1 rows gid (gate i or g), c2/c3 rows gid+8 (f or o)
                float pi = acc[0][n][0 + s] + xx * wih[0] + bia[0];
                float pf = acc[0][n][2 + s] + xx * wih[1] + bia[1];
                float pg = acc[1][n][0 + s] + xx * wih[2] + bia[2];
                float po = acc[1][n][2 + s] + xx * wih[3] + bia[3];
                float ig = sigf(pi);
                float fg = sigf(pf);
                float gg = tanf_(pg);
                float og = sigf(po);
                float cc = fg * cst[n * 2 + s] + ig * gg;
                cst[n * 2 + s] = cc;
                float hh = og * tanf_(cc);
                h_sm[b * HSTRIDE + j] = __float2half(hh);
                if (last) hf_sm[b * 128 + j] = hh;
            }
        }
        __syncthreads();   // h_{t+1} published
    }

    // final per-channel Linear(H,1) from fp32 h_T
    if (tid < 64) {
        int b = tid;
        float s = b_fc[ch];
        const float* wf = W_fc + ch * 128;
        #pragma unroll 8
        for (int jj = 0; jj < 128; ++jj)
            s += wf[jj] * hf_sm[b * 128 + jj];
        out[((size_t)(btile * 64 + b)) * Csz + ch] = s;
    }
}

extern "C" void kernel_launch(void* const* d_in, const int* in_sizes, int n_in,
                              void* d_out, int out_size)
{
    const float* x    = (const float*)d_in[0];
    const float* W_ih = (const float*)d_in[1];
    const float* W_hh = (const float*)d_in[2];
    const float* b_ih = (const float*)d_in[3];
    const float* b_hh = (const float*)d_in[4];
    const float* W_fc = (const float*)d_in[5];
    const float* b_fc = (const float*)d_in[6];
    float* out = (float*)d_out;

    cudaFuncSetAttribute(lstm_fused_kernel,
                         cudaFuncAttributeMaxDynamicSharedMemorySize, SMEM_TOTAL);

    dim3 grid(Bsz / BTILE, Csz);   // (8, 64) = 512 CTAs
    lstm_fused_kernel<<<grid, NTHR, SMEM_TOTAL>>>(x, W_ih, W_hh, b_ih, b_hh,
                                                  W_fc, b_fc, out);
}

// round 9
// speedup vs baseline: 1.3256x; 1.3256x over previous
#include <cuda_runtime.h>
#include <cuda_fp16.h>
#include <stdint.h>

#define Bsz 512
#define Tsz 1024
#define Csz 64
#define Hsz 128

static const int BTILE   = 64;
static const int NTHR    = 512;   // 16 warps
static const int HSTRIDE = 136;   // halves per batch row (128 + 8 pad) -> 272B, conflict-free

// dynamic smem (bytes):
//   [0,131072)        W fp16 A-fragment-ready (pre-scaled: i,f,o rows *0.5)
//   [131072,+17408)   h buf0 fp16 (64 x 136)
//   [148480,+17408)   h buf1 fp16
//   [165888,+512)     x_sm fp32 (2 x 64)
//   [166400,+32768)   hf_sm fp32 (64 x 128) final h for fc
static const int SMEM_H0 = 131072;
static const int SMEM_H1 = SMEM_H0 + 17408;
static const int SMEM_X  = SMEM_H1 + 17408;
static const int SMEM_HF = SMEM_X + 512;
static const int SMEM_TOTAL = SMEM_HF + 32768;   // 199168 B

__device__ __forceinline__ unsigned pack2(float a, float b) {
    __half2 h = __floats2half2_rn(a, b);
    return *reinterpret_cast<unsigned*>(&h);
}

__device__ __forceinline__ void mma16816(float* c, uint4 a, unsigned b0, unsigned b1) {
    asm volatile(
        "mma.sync.aligned.m16n8k16.row.col.f32.f16.f16.f32 "
        "{%0,%1,%2,%3}, {%4,%5,%6,%7}, {%8,%9}, {%0,%1,%2,%3};\n"
        : "+f"(c[0]), "+f"(c[1]), "+f"(c[2]), "+f"(c[3])
        : "r"(a.x), "r"(a.y), "r"(a.z), "r"(a.w), "r"(b0), "r"(b1));
}

__device__ __forceinline__ void ldsm_x4(unsigned& r0, unsigned& r1,
                                        unsigned& r2, unsigned& r3, uint32_t addr) {
    asm volatile("ldmatrix.sync.aligned.m8n8.x4.shared.b16 {%0,%1,%2,%3}, [%4];"
        : "=r"(r0), "=r"(r1), "=r"(r2), "=r"(r3) : "r"(addr));
}

__device__ __forceinline__ float tanh_apx(float x) {
    float y; asm("tanh.approx.f32 %0, %1;" : "=f"(y) : "f"(x)); return y;
}

extern __shared__ unsigned char smem_raw[];

__global__ void __launch_bounds__(NTHR, 1)
lstm_fused_kernel(const float* __restrict__ x,     // [B,T,C]
                  const float* __restrict__ W_ih,  // [C,4H]
                  const float* __restrict__ W_hh,  // [C,4H,H]
                  const float* __restrict__ b_ih,  // [C,4H]
                  const float* __restrict__ b_hh,  // [C,4H]
                  const float* __restrict__ W_fc,  // [C,H]
                  const float* __restrict__ b_fc,  // [C]
                  float* __restrict__ out)         // [B,C]
{
    const int btile = blockIdx.x;   // 0..7
    const int ch    = blockIdx.y;   // 0..63
    const int tid   = threadIdx.x;
    const int w     = tid >> 5;
    const int l     = tid & 31;
    const int gid   = l >> 2;       // 0..7
    const int q     = l & 3;        // 0..3

    __half* Wfr   = (__half*)(smem_raw);
    __half* h_sm0 = (__half*)(smem_raw + SMEM_H0);
    __half* h_sm1 = (__half*)(smem_raw + SMEM_H1);
    float*  x_sm  = (float*)(smem_raw + SMEM_X);
    float*  hf_sm = (float*)(smem_raw + SMEM_HF);

    const int j = 8 * w + gid;   // hidden unit owned by this lane group

    // ---- Stage W_hh[ch] fp16 A-fragment-ready, gate-interleaved rows,
    //      sigmoid-gate rows (i,f,o) pre-scaled by 0.5 for tanh-identity sigmoid ----
    {
        const float* Wc = W_hh + (size_t)ch * (4 * Hsz * Hsz);
        #pragma unroll
        for (int mt = 0; mt < 2; ++mt) {
            #pragma unroll
            for (int ks = 0; ks < 8; ++ks) {
                unsigned u[4];
                #pragma unroll
                for (int p = 0; p < 4; ++p) {
                    // p0:(gid,2q) p1:(gid+8,2q) p2:(gid,2q+8) p3:(gid+8,2q+8)
                    int r16 = (p & 1) ? (gid + 8) : gid;
                    int kk  = ks * 16 + q * 2 + ((p & 2) ? 8 : 0);
                    int G   = mt * 2 + (r16 >= 8 ? 1 : 0);  // 0:i 1:f 2:g 3:o
                    int row = G * 128 + 8 * w + (r16 & 7);
                    float sc = (G == 2) ? 1.0f : 0.5f;
                    float2 v = *(const float2*)(Wc + row * Hsz + kk);
                    u[p] = pack2(v.x * sc, v.y * sc);
                }
                uint4 frag; frag.x = u[0]; frag.y = u[1]; frag.z = u[2]; frag.w = u[3];
                int fidx = ((w * 2 + mt) * 8 + ks) * 32 + l;
                *(uint4*)(Wfr + fidx * 8) = frag;
            }
        }
    }

    // per-lane input weight + combined bias (sigmoid gates pre-scaled by 0.5)
    float wih[4], bia[4];
    #pragma unroll
    for (int G = 0; G < 4; ++G) {
        int row = G * 128 + j;
        float sc = (G == 2) ? 1.0f : 0.5f;
        wih[G] = W_ih[ch * 512 + row] * sc;
        bia[G] = (b_ih[ch * 512 + row] + b_hh[ch * 512 + row]) * sc;
    }

    // ldmatrix lane addresses: 4 x (x4 load) per ks, covering n-tiles (2v, 2v+1)
    const int mi = l >> 3;         // matrix index 0..3
    const int rr = l & 7;
    uint32_t loff[4];
    #pragma unroll
    for (int v = 0; v < 4; ++v) {
        int b = 16 * v + ((mi >> 1) << 3) + rr;
        loff[v] = (uint32_t)((b * HSTRIDE + (mi & 1) * 8) * 2);   // bytes
    }
    const uint32_t h0a = (uint32_t)__cvta_generic_to_shared(h_sm0);
    const uint32_t h1a = (uint32_t)__cvta_generic_to_shared(h_sm1);
    const uint32_t wfa = (uint32_t)__cvta_generic_to_shared(Wfr);
    (void)wfa;

    // zero h buf0 (pad bytes never read by ldmatrix: max row offset 240+16 <= 272)
    for (int i = tid; i < BTILE * HSTRIDE; i += NTHR) h_sm0[i] = __float2half(0.0f);

    float cst[16];
    #pragma unroll
    for (int i = 0; i < 16; ++i) cst[i] = 0.0f;

    const float* xb = x + ((size_t)(btile * 64) * Tsz) * Csz + ch;

    // preload x_0 into x_sm[0]
    if (tid < 64) x_sm[tid] = __ldg(xb + ((size_t)tid * Tsz) * Csz);
    __syncthreads();

    #pragma unroll 1
    for (int t = 0; t < Tsz; ++t) {
        // prefetch x_{t+1}
        float xv = 0.0f;
        if (tid < 64 && t + 1 < Tsz)
            xv = __ldg(xb + ((size_t)tid * Tsz + (t + 1)) * Csz);

        const uint32_t hb = (t & 1) ? h1a : h0a;

        float acc[2][8][4];
        #pragma unroll
        for (int mt = 0; mt < 2; ++mt)
            #pragma unroll
            for (int n = 0; n < 8; ++n)
                #pragma unroll
                for (int r = 0; r < 4; ++r) acc[mt][n][r] = 0.0f;

        // gates[512x64] = W_hh * h_t  (read h buf t&1)
        #pragma unroll
        for (int ks = 0; ks < 8; ++ks) {
            uint4 A0 = *(const uint4*)(Wfr + (((w * 2 + 0) * 8 + ks) * 32 + l) * 8);
            uint4 A1 = *(const uint4*)(Wfr + (((w * 2 + 1) * 8 + ks) * 32 + l) * 8);
            #pragma unroll
            for (int v = 0; v < 4; ++v) {
                unsigned b0a, b1a, b0b, b1b;
                ldsm_x4(b0a, b1a, b0b, b1b, hb + loff[v] + ks * 32);
                mma16816(acc[0][2 * v    ], A0, b0a, b1a);
                mma16816(acc[1][2 * v    ], A1, b0a, b1a);
                mma16816(acc[0][2 * v + 1], A0, b0b, b1b);
                mma16816(acc[1][2 * v + 1], A1, b0b, b1b);
            }
        }

        if (tid < 64) x_sm[((t + 1) & 1) * 64 + tid] = xv;

        __half* h_next = (t & 1) ? h_sm0 : h_sm1;   // write buf (t+1)&1
        const float* x_cur = x_sm + (t & 1) * 64;
        const bool last = (t == Tsz - 1);

        #pragma unroll
        for (int n = 0; n < 8; ++n) {
            #pragma unroll
            for (int s = 0; s < 2; ++s) {
                int b = n * 8 + q * 2 + s;
                float xx = x_cur[b];
                // preacts (i,f,o already scaled by 0.5 via weights/bias)
                float pi = acc[0][n][0 + s] + xx * wih[0] + bia[0];
                float pf = acc[0][n][2 + s] + xx * wih[1] + bia[1];
                float pg = acc[1][n][0 + s] + xx * wih[2] + bia[2];
                float po = acc[1][n][2 + s] + xx * wih[3] + bia[3];
                float ig = 0.5f * tanh_apx(pi) + 0.5f;
                float fg = 0.5f * tanh_apx(pf) + 0.5f;
                float gg = tanh_apx(pg);
                float og = 0.5f * tanh_apx(po) + 0.5f;
                float cc = fg * cst[n * 2 + s] + ig * gg;
                cst[n * 2 + s] = cc;
                float hh = og * tanh_apx(cc);
                h_next[b * HSTRIDE + j] = __float2half(hh);
                if (last) hf_sm[b * 128 + j] = hh;
            }
        }
        __syncthreads();   // publish h_{t+1}, x_{t+1}
    }

    // per-channel Linear(H,1) on fp32 h_T
    if (tid < 64) {
        int b = tid;
        float s = b_fc[ch];
        const float* wf = W_fc + ch * 128;
        #pragma unroll 8
        for (int jj = 0; jj < 128; ++jj)
            s += wf[jj] * hf_sm[b * 128 + jj];
        out[((size_t)(btile * 64 + b)) * Csz + ch] = s;
    }
}

extern "C" void kernel_launch(void* const* d_in, const int* in_sizes, int n_in,
                              void* d_out, int out_size)
{
    const float* x    = (const float*)d_in[0];
    const float* W_ih = (const float*)d_in[1];
    const float* W_hh = (const float*)d_in[2];
    const float* b_ih = (const float*)d_in[3];
    const float* b_hh = (const float*)d_in[4];
    const float* W_fc = (const float*)d_in[5];
    const float* b_fc = (const float*)d_in[6];
    float* out = (float*)d_out;

    cudaFuncSetAttribute(lstm_fused_kernel,
                         cudaFuncAttributeMaxDynamicSharedMemorySize, SMEM_TOTAL);

    dim3 grid(Bsz / BTILE, Csz);   // (8, 64) = 512 CTAs
    lstm_fused_kernel<<<grid, NTHR, SMEM_TOTAL>>>(x, W_ih, W_hh, b_ih, b_hh,
                                                  W_fc, b_fc, out);
}